// round 13
// baseline (speedup 1.0000x reference)
#include <cuda_runtime.h>
#include <cuda_bf16.h>

// Ball query: for each of NQ=32768 query points (p_grid), find first K=10
// points of x (NP=8192) with d2 <= RADIUS^2, ascending index order.
//
// Output buffer (float32), out_size = NQ*K + NQ*K*3:
//   [0 .. NQ*K)        mapping (index as float, 0 if not found)
//   [NQ*K .. NQ*K*4)   gathered coords (x[mapping], zeroed if not found)
//
// R13 = R6 inner loop (64-pt chunks, best proven) + per-CTA SMEM work queue:
// each CTA owns a 37-query slice; its 8 warps draw queries dynamically from
// an SMEM counter with the next ticket prefetched (atomic off critical path).
// Kills the per-warp straggler tail without R7's global-atomic poison.

#define NP 8192
#define NQ 32768
#define KNN 10
#define R2C 0.0625f
#define MAP_ELEMS (NQ * KNN)
#define NPC 2048            // points cached in SMEM (32 KB as float4)
#define WARPS_PER_CTA 8
#define QPB 37              // queries per CTA: 888 * 37 = 32856 >= 32768

__global__ void __launch_bounds__(256)
bq_kernel(const float* __restrict__ x,
          const float* __restrict__ pg,
          float* __restrict__ out)
{
    __shared__ float4 pts[NPC];                       // 32 KB
    __shared__ int scratch[WARPS_PER_CTA][16];        // hit indices (10 used)
    __shared__ unsigned s_ctr;

    if (threadIdx.x == 0) s_ctr = 0;
    for (int i = threadIdx.x; i < NPC; i += blockDim.x) {
        const float px = x[3 * i + 0];
        const float py = x[3 * i + 1];
        const float pz = x[3 * i + 2];
        const float ps = px * px + py * py + pz * pz;
        pts[i] = make_float4(px, py, pz, ps);
    }
    __syncthreads();

    const int lane = threadIdx.x & 31;
    const int warp = threadIdx.x >> 5;
    const unsigned lt_mask = (1u << lane) - 1u;

    const unsigned qbase = blockIdx.x * QPB;
    const unsigned qlim  = (qbase + QPB < NQ) ? qbase + QPB : NQ;

    unsigned nxt = 0;
    if (lane == 0) nxt = atomicAdd(&s_ctr, 1u);

    for (;;) {
        const unsigned qi = __shfl_sync(0xffffffffu, nxt, 0);
        const unsigned q  = qbase + qi;
        if (q >= qlim) break;
        // prefetch next ticket: ATOMS latency hidden behind this query's scan
        if (lane == 0) nxt = atomicAdd(&s_ctr, 1u);

        const float qx = pg[3 * q + 0];
        const float qy = pg[3 * q + 1];
        const float qz = pg[3 * q + 2];
        const float q2 = qx * qx + qy * qy + qz * qz;

        int cnt = 0;

        // ---- phase 1: SMEM-cached prefix, 64 pts / iteration ----
        for (int base = 0; base < NPC; base += 64) {
            const float4 A = pts[base + lane];
            const float4 B = pts[base + 32 + lane];

            const float dotA = qx * A.x + qy * A.y + qz * A.z;
            const float d2A  = q2 + A.w - 2.0f * dotA;
            const float dotB = qx * B.x + qy * B.y + qz * B.z;
            const float d2B  = q2 + B.w - 2.0f * dotB;

            const bool vA = (d2A <= R2C);
            const bool vB = (d2B <= R2C);
            const unsigned mA = __ballot_sync(0xffffffffu, vA);
            const unsigned mB = __ballot_sync(0xffffffffu, vB);

            if (mA | mB) {        // warp-uniform: skip slot code on empty chunk
                if (vA) {
                    const int slot = cnt + __popc(mA & lt_mask);
                    if (slot < KNN) scratch[warp][slot] = base + lane;
                }
                const int cA = cnt + __popc(mA);
                if (vB) {
                    const int slot = cA + __popc(mB & lt_mask);
                    if (slot < KNN) scratch[warp][slot] = base + 32 + lane;
                }
                cnt = cA + __popc(mB);
                if (cnt >= KNN) break;   // warp-uniform
            }
        }

        // ---- phase 2 (rare): tail from global, identical math ----
        if (cnt < KNN) {
            for (int base = NPC; base < NP; base += 32) {
                const int i = base + lane;
                const float px = x[3 * i + 0];
                const float py = x[3 * i + 1];
                const float pz = x[3 * i + 2];
                const float ps  = px * px + py * py + pz * pz;
                const float dot = qx * px + qy * py + qz * pz;
                const float d2  = q2 + ps - 2.0f * dot;
                const bool valid = (d2 <= R2C);
                const unsigned mask = __ballot_sync(0xffffffffu, valid);
                if (valid) {
                    const int slot = cnt + __popc(mask & lt_mask);
                    if (slot < KNN) scratch[warp][slot] = i;
                }
                cnt += __popc(mask);
                if (cnt >= KNN) break;
            }
        }

        __syncwarp();   // make scratch STS visible to all lanes

        // ---- epilogue: lanes 0..9 emit mapping + coords ----
        const int c = cnt < KNN ? cnt : KNN;
        if (lane < KNN) {
            const bool found = (lane < c);
            const int idx = found ? scratch[warp][lane] : 0;
            out[(size_t)q * KNN + lane] = found ? (float)idx : 0.0f;

            float px = 0.0f, py = 0.0f, pz = 0.0f;
            if (found) {
                if (idx < NPC) {
                    const float4 t = pts[idx];
                    px = t.x; py = t.y; pz = t.z;
                } else {
                    px = x[3 * idx + 0];
                    py = x[3 * idx + 1];
                    pz = x[3 * idx + 2];
                }
            }
            float* oc = out + MAP_ELEMS + ((size_t)q * KNN + lane) * 3;
            oc[0] = px; oc[1] = py; oc[2] = pz;
        }
        __syncwarp();   // scratch reuse safety for next query
    }
}

extern "C" void kernel_launch(void* const* d_in, const int* in_sizes, int n_in,
                              void* d_out, int out_size)
{
    const float* x  = (const float*)d_in[0];   // (1, 8192, 3)
    const float* pg = (const float*)d_in[1];   // (1, 64, 32, 16, 3)
    if (n_in >= 2 && in_sizes[0] == NQ * 3 && in_sizes[1] == NP * 3) {
        const float* t = x; x = pg; pg = t;
    }
    float* out = (float*)d_out;

    static bool attr_set = false;
    if (!attr_set) {
        cudaFuncSetAttribute(bq_kernel,
                             cudaFuncAttributePreferredSharedMemoryCarveout, 100);
        attr_set = true;
    }

    const int threads = 256;
    const int blocks  = 888;    // 6 CTAs/SM x 148 SMs = single wave

    bq_kernel<<<blocks, threads>>>(x, pg, out);
}